// round 8
// baseline (speedup 1.0000x reference)
#include <cuda_runtime.h>
#include <cuda_fp16.h>
#include <cstdint>

#define EPS 1e-5f

// ---- problem sizes ----
#define BB 64
#define NN 64
#define DD 64
#define TT 128
#define HG 256
#define RTOT (BB*NN*NN)   // 262144 pair rows

// ---- big-GEMM tiling ----
#define MT 256
#define NT 128
#define KC 128            // K chunk held in smem (2 chunks cover K=256)
#define LDSK 136          // half stride (128 + 8 pad) -> conflict-free LDSM

// ---- device scratch (static: no allocation allowed) ----
__device__ float g_A [BB*NN*HG];     // x @ W0_top   (4096 x 256) fp32 exact
__device__ float g_Bm[BB*NN*HG];     // x @ W0_bot
__device__ float g_SA[BB*HG];
__device__ float g_SB[BB*HG];
// stats: QA[0:256] QB[256:512] S1[512:768] Q1[768:1024] S2[1024:1152] Q2[1152:1280]
__device__ float g_stats[1536];
// coef: u0[0:256] v0[256:512] u1[512:768] v1[768:1024] u2[1024:1152] v2[1152:1280]
__device__ float g_coef[1536];
__device__ float g_z1[(size_t)RTOT*HG];   // 268 MB fp32
__device__ float g_z2[(size_t)RTOT*TT];   // 134 MB fp32
__device__ float g_part[512*TT];
__device__ float g_y1[BB*TT];
__device__ float g_y2[BB*TT];
// W pre-split fp16 hi/lo, n-major [n][k]
__device__ __half g_W1t_hi[HG*HG], g_W1t_lo[HG*HG];
__device__ __half g_W2t_hi[TT*HG], g_W2t_lo[TT*HG];

// ---------------------------------------------------------------------------
__device__ __forceinline__ void mma16816(float* c, const uint32_t* a, const uint32_t* b) {
    asm volatile(
        "mma.sync.aligned.m16n8k16.row.col.f32.f16.f16.f32 "
        "{%0,%1,%2,%3}, {%4,%5,%6,%7}, {%8,%9}, {%0,%1,%2,%3};\n"
        : "+f"(c[0]), "+f"(c[1]), "+f"(c[2]), "+f"(c[3])
        : "r"(a[0]), "r"(a[1]), "r"(a[2]), "r"(a[3]), "r"(b[0]), "r"(b[1]));
}

__device__ __forceinline__ void ldsm4(uint32_t* r, uint32_t addr) {
    asm volatile("ldmatrix.sync.aligned.m8n8.x4.shared.b16 {%0,%1,%2,%3}, [%4];"
                 : "=r"(r[0]), "=r"(r[1]), "=r"(r[2]), "=r"(r[3]) : "r"(addr));
}

__device__ __forceinline__ uint32_t smem_u32(const void* p) {
    uint32_t a;
    asm("{ .reg .u64 t; cvta.to.shared.u64 t, %1; cvt.u32.u64 %0, t; }" : "=r"(a) : "l"(p));
    return a;
}

// split fp32 -> (hi, lo) fp16 pair
__device__ __forceinline__ void split_h(float v, __half& hi, __half& lo) {
    hi = __float2half_rn(v);
    lo = __float2half_rn(v - __half2float(hi));
}

// ---------------------------------------------------------------------------
// K0: split W1/W2 to fp16 hi/lo, transposed to n-major [n][k]
__global__ void k0_splitW(const float* __restrict__ gW1, const float* __restrict__ gW2) {
    int n = blockIdx.x, k = threadIdx.x;  // k 0..255
    if (n < 256) {
        float w = gW1[k*HG + n];
        __half h, l; split_h(w, h, l);
        g_W1t_hi[n*HG + k] = h; g_W1t_lo[n*HG + k] = l;
    } else {
        int n2 = n - 256;  // 0..127
        float w = gW2[k*TT + n2];
        __half h, l; split_h(w, h, l);
        g_W2t_hi[n2*HG + k] = h; g_W2t_lo[n2*HG + k] = l;
    }
}

// K1: A = x @ W0[0:64,:], Bm = x @ W0[64:128,:]; per-batch sums SA/SB; global
// sums of squares QA/QB. One CTA per batch b, 256 threads = cols. All fp32.
__global__ void k1_computeAB(const float* __restrict__ x, const float* __restrict__ gW0) {
    __shared__ float xs[NN*DD];
    int b = blockIdx.x;
    int c = threadIdx.x;
    for (int idx = threadIdx.x; idx < NN*DD; idx += blockDim.x)
        xs[idx] = x[b*NN*DD + idx];
    __syncthreads();
    float sa = 0.f, sb = 0.f, qa = 0.f, qb = 0.f;
    for (int rc = 0; rc < 2; rc++) {
        float accA[32], accB[32];
        #pragma unroll
        for (int r = 0; r < 32; r++) { accA[r] = 0.f; accB[r] = 0.f; }
        for (int k = 0; k < DD; k++) {
            float wA = gW0[k*HG + c];
            float wB = gW0[(DD + k)*HG + c];
            #pragma unroll
            for (int r = 0; r < 32; r++) {
                float xv = xs[(rc*32 + r)*DD + k];
                accA[r] += xv * wA;
                accB[r] += xv * wB;
            }
        }
        #pragma unroll
        for (int r = 0; r < 32; r++) {
            int row = rc*32 + r;
            g_A [(b*NN + row)*HG + c] = accA[r];
            g_Bm[(b*NN + row)*HG + c] = accB[r];
            sa += accA[r]; qa += accA[r]*accA[r];
            sb += accB[r]; qb += accB[r]*accB[r];
        }
    }
    g_SA[b*HG + c] = sa;
    g_SB[b*HG + c] = sb;
    atomicAdd(&g_stats[c],      qa);
    atomicAdd(&g_stats[HG + c], qb);
}

// K2: layer-0 BN stats via pair factorization; fold into (u0, v0)
__global__ void k2_finalize0(const float* __restrict__ gb0, const float* __restrict__ gg0,
                             const float* __restrict__ gB0) {
    int c = threadIdx.x;
    float sat = 0.f, sbt = 0.f, p = 0.f;
    for (int b = 0; b < BB; b++) {
        float a = g_SA[b*HG + c], bm = g_SB[b*HG + c];
        sat += a; sbt += bm; p += a*bm;
    }
    float QA = g_stats[c], QB = g_stats[HG + c];
    float g  = gb0[c];
    const float Rf = (float)RTOT;
    float mean = (NN*(sat + sbt))/Rf + g;
    float esq  = (NN*QA + NN*QB + 2.f*p + 2.f*g*NN*(sat + sbt) + Rf*g*g)/Rf;
    float var  = esq - mean*mean;
    float u = gg0[c] * rsqrtf(var + EPS);
    g_coef[c]      = u;
    g_coef[HG + c] = u*(g - mean) + gB0[c];
}

// ---------------------------------------------------------------------------
// Big fused GEMM, split-fp16 3-MMA (fp32-accurate), ldmatrix fragment loads.
// Warp tile 64x64 (8 warps, 4 mw x 2 nw): 96 HMMA per 16 LDSM per k-slice,
// B-fragment duplication x4 (was x8) -> crossbar 64KB per CTA per k-slice.
extern __shared__ char smem_raw[];

// smem offsets (bytes)
#define SM_HHI 0
#define SM_HLO (MT*LDSK*2)                 // 69632
#define SM_WHI (2*MT*LDSK*2)               // 139264
#define SM_WLO (SM_WHI + NT*LDSK*2)        // 174080
#define SM_CU  (SM_WLO + NT*LDSK*2)        // 208896
#define SM_CV  (SM_CU + 256*4)
#define SM_SSUM (SM_CV + 256*4)
#define SM_SSQ  (SM_SSUM + 128*4)
#define SM_TOT  (SM_SSQ + 128*4)           // 211968

template<int LAYER>
__global__ __launch_bounds__(256, 1) void k_biggemm() {
    float*  cu  = (float*)(smem_raw + SM_CU);
    float*  cv  = (float*)(smem_raw + SM_CV);
    float*  ssum = (float*)(smem_raw + SM_SSUM);
    float*  ssq  = (float*)(smem_raw + SM_SSQ);

    int tid = threadIdx.x;
    int r0  = blockIdx.x * MT;
    int c0  = blockIdx.y * NT;

    {
        const int coff = (LAYER == 1) ? 0 : 512;
        for (int i = tid; i < 256; i += blockDim.x) {
            cu[i] = g_coef[coff + i];
            cv[i] = g_coef[coff + 256 + i];
        }
        for (int i = tid; i < 128; i += blockDim.x) { ssum[i] = 0.f; ssq[i] = 0.f; }
    }
    __syncthreads();

    int lane = tid & 31, wid = tid >> 5;
    int mw = wid & 3, nw = wid >> 2;           // 4 row-warps x 2 col-warps
    int gq = lane >> 2, tq = lane & 3;

    float acc[4][8][4];
    #pragma unroll
    for (int a = 0; a < 4; a++)
        #pragma unroll
        for (int s = 0; s < 8; s++)
            #pragma unroll
            for (int d = 0; d < 4; d++) acc[a][s][d] = 0.f;

    // LDSM per-lane base addresses (byte offsets into smem)
    const uint32_t sb = smem_u32(smem_raw);
    const uint32_t aRow = (uint32_t)(mw*64 + (lane & 7) + ((lane >> 3) & 1)*8);
    const uint32_t aKof = (uint32_t)(((lane >> 4) & 1)*8);
    const uint32_t aOff = (aRow*LDSK + aKof)*2;
    const uint32_t bRow = (uint32_t)(nw*64 + (lane & 7) + ((lane >> 4) & 1)*8);
    const uint32_t bKof = (uint32_t)(((lane >> 3) & 1)*8);
    const uint32_t bOff = (bRow*LDSK + bKof)*2;
    const uint32_t aHi = sb + SM_HHI + aOff, aLo = sb + SM_HLO + aOff;
    const uint32_t bHi = sb + SM_WHI + bOff, bLo = sb + SM_WLO + bOff;

    const __half* wh = (LAYER == 1) ? (g_W1t_hi + (size_t)c0*HG) : g_W2t_hi;
    const __half* wl = (LAYER == 1) ? (g_W1t_lo + (size_t)c0*HG) : g_W2t_lo;
    const int b = r0 >> 12;
    const int ibase = (r0 >> 6) & 63;

    for (int kc = 0; kc < 2; kc++) {
        if (kc) __syncthreads();   // prior chunk's mma consumers done
        const int kbase = kc * KC;

        // ---- build h tile (MT x KC), hi/lo split: 8192 x4-items / 256 thr ----
        for (int idx = tid; idx < 8192; idx += 256) {
            int r = idx >> 5, c = (idx & 31)*4, cc = kbase + c;
            float v0f, v1f, v2f, v3f;
            if (LAYER == 1) {
                int i = ibase + (r >> 6), j = r & 63;
                float4 av = *(const float4*)&g_A [(size_t)(b*NN + i)*HG + cc];
                float4 bv = *(const float4*)&g_Bm[(size_t)(b*NN + j)*HG + cc];
                v0f = fmaxf(cu[cc  ]*(av.x + bv.x) + cv[cc  ], 0.f);
                v1f = fmaxf(cu[cc+1]*(av.y + bv.y) + cv[cc+1], 0.f);
                v2f = fmaxf(cu[cc+2]*(av.z + bv.z) + cv[cc+2], 0.f);
                v3f = fmaxf(cu[cc+3]*(av.w + bv.w) + cv[cc+3], 0.f);
            } else {
                float4 z = *(const float4*)&g_z1[(size_t)(r0 + r)*HG + cc];
                v0f = fmaxf(cu[cc  ]*z.x + cv[cc  ], 0.f);
                v1f = fmaxf(cu[cc+1]*z.y + cv[cc+1], 0.f);
                v2f = fmaxf(cu[cc+2]*z.z + cv[cc+2], 0.f);
                v3f = fmaxf(cu[cc+3]*z.w + cv[cc+3], 0.f);
            }
            __half h0,l0,h1,l1,h2,l2,h3,l3;
            split_h(v0f,h0,l0); split_h(v1f,h1,l1); split_h(v2f,h2,l2); split_h(v3f,h3,l3);
            uint32_t o = (uint32_t)(r*LDSK + c)*2;
            *(__half2*)(smem_raw + SM_HHI + o)     = __halves2half2(h0, h1);
            *(__half2*)(smem_raw + SM_HHI + o + 4) = __halves2half2(h2, h3);
            *(__half2*)(smem_raw + SM_HLO + o)     = __halves2half2(l0, l1);
            *(__half2*)(smem_raw + SM_HLO + o + 4) = __halves2half2(l2, l3);
        }
        // ---- W chunk (NT n-rows x KC k), pre-split halves, 16B copies ----
        for (int idx = tid; idx < 2048; idx += 256) {
            int n = idx >> 4, ch = (idx & 15)*8;
            uint32_t o = (uint32_t)(n*LDSK + ch)*2;
            *(uint4*)(smem_raw + SM_WHI + o) = *(const uint4*)(wh + (size_t)n*HG + kbase + ch);
            *(uint4*)(smem_raw + SM_WLO + o) = *(const uint4*)(wl + (size_t)n*HG + kbase + ch);
        }
        __syncthreads();

        // ---- mma loop: 16 LDSM feed 96 HMMA per k-slice ----
        for (int ko = 0; ko < KC; ko += 16) {
            uint32_t afh[4][4], afl[4][4];
            #pragma unroll
            for (int mi = 0; mi < 4; mi++) {
                ldsm4(afh[mi], aHi + (uint32_t)(mi*16*LDSK + ko)*2);
                ldsm4(afl[mi], aLo + (uint32_t)(mi*16*LDSK + ko)*2);
            }
            #pragma unroll
            for (int sp = 0; sp < 4; sp++) {
                uint32_t bh[4], bl[4];
                ldsm4(bh, bHi + (uint32_t)(sp*16*LDSK + ko)*2);
                ldsm4(bl, bLo + (uint32_t)(sp*16*LDSK + ko)*2);
                // term 0: hi*hi  (8 independent accumulators)
                #pragma unroll
                for (int si = 0; si < 2; si++)
                    #pragma unroll
                    for (int mi = 0; mi < 4; mi++)
                        mma16816(acc[mi][sp*2+si], afh[mi], bh + 2*si);
                // term 1: lo*hi
                #pragma unroll
                for (int si = 0; si < 2; si++)
                    #pragma unroll
                    for (int mi = 0; mi < 4; mi++)
                        mma16816(acc[mi][sp*2+si], afl[mi], bh + 2*si);
                // term 2: hi*lo
                #pragma unroll
                for (int si = 0; si < 2; si++)
                    #pragma unroll
                    for (int mi = 0; mi < 4; mi++)
                        mma16816(acc[mi][sp*2+si], afh[mi], bl + 2*si);
            }
        }
    }

    // ---- epilogue: fp32 store + BN stats ----
    const int ldo = (LAYER == 1) ? HG : TT;
    float* zout = (LAYER == 1) ? g_z1 : g_z2;
    float csum[16], csq[16];
    #pragma unroll
    for (int q = 0; q < 16; q++) { csum[q] = 0.f; csq[q] = 0.f; }
    #pragma unroll
    for (int mi = 0; mi < 4; mi++) {
        int rA = r0 + mw*64 + mi*16 + gq;
        #pragma unroll
        for (int s = 0; s < 8; s++) {
            int cA = c0 + nw*64 + s*8 + 2*tq;
            float d0 = acc[mi][s][0], d1 = acc[mi][s][1], d2 = acc[mi][s][2], d3 = acc[mi][s][3];
            *(float2*)&zout[(size_t)rA*ldo + cA]       = make_float2(d0, d1);
            *(float2*)&zout[(size_t)(rA + 8)*ldo + cA] = make_float2(d2, d3);
            csum[2*s]   += d0 + d2; csq[2*s]   += d0*d0 + d2*d2;
            csum[2*s+1] += d1 + d3; csq[2*s+1] += d1*d1 + d3*d3;
        }
    }
    #pragma unroll
    for (int q = 0; q < 16; q++) {
        #pragma unroll
        for (int off = 4; off < 32; off <<= 1) {
            csum[q] += __shfl_xor_sync(0xffffffffu, csum[q], off);
            csq[q]  += __shfl_xor_sync(0xffffffffu, csq[q],  off);
        }
    }
    if (lane < 4) {
        #pragma unroll
        for (int q = 0; q < 16; q++) {
            int cl = nw*64 + (q >> 1)*8 + 2*tq + (q & 1);
            atomicAdd(&ssum[cl], csum[q]);
            atomicAdd(&ssq[cl],  csq[q]);
        }
    }
    __syncthreads();
    const int soff  = (LAYER == 1) ? 512 : 1024;
    const int sqoff = (LAYER == 1) ? 768 : 1152;
    if (tid < NT) {
        atomicAdd(&g_stats[soff  + c0 + tid], ssum[tid]);
        atomicAdd(&g_stats[sqoff + c0 + tid], ssq[tid]);
    }
}

// K4/K6: fold BN stats into (u, v). Linear bias before BN cancels exactly.
__global__ void k4_finalize1(const float* __restrict__ gg1, const float* __restrict__ gB1) {
    int c = threadIdx.x;  // 256
    float S = g_stats[512 + c], Q = g_stats[768 + c];
    float mean = S / (float)RTOT;
    float var  = Q / (float)RTOT - mean*mean;
    float u = gg1[c] * rsqrtf(var + EPS);
    g_coef[512 + c] = u;
    g_coef[768 + c] = gB1[c] - mean*u;
}
__global__ void k6_finalize2(const float* __restrict__ gg2, const float* __restrict__ gB2) {
    int c = threadIdx.x;  // 128
    float S = g_stats[1024 + c], Q = g_stats[1152 + c];
    float mean = S / (float)RTOT;
    float var  = Q / (float)RTOT - mean*mean;
    float u = gg2[c] * rsqrtf(var + EPS);
    g_coef[1024 + c] = u;
    g_coef[1152 + c] = gB2[c] - mean*u;
}

// K7: pair-sum reduction s[b,c] = sum_p relu(u2*z2 + v2); 8 partial slots per b
__global__ void k7_reduce() {
    __shared__ float red[4][128];
    int b = blockIdx.x, slot = blockIdx.y;
    int c2 = threadIdx.x & 63, rg = threadIdx.x >> 6;
    int c = 2*c2;
    float ua = g_coef[1024 + c], ub = g_coef[1024 + c + 1];
    float va = g_coef[1152 + c], vb = g_coef[1152 + c + 1];
    size_t base = ((size_t)b*4096 + slot*512 + rg*128) * TT;
    float s0 = 0.f, s1 = 0.f;
    for (int rr = 0; rr < 128; rr++) {
        float2 z = *(const float2*)&g_z2[base + (size_t)rr*TT + c];
        s0 += fmaxf(ua*z.x + va, 0.f);
        s1 += fmaxf(ub*z.y + vb, 0.f);
    }
    red[rg][c] = s0; red[rg][c + 1] = s1;
    __syncthreads();
    if (threadIdx.x < 128) {
        float t = red[0][threadIdx.x] + red[1][threadIdx.x] + red[2][threadIdx.x] + red[3][threadIdx.x];
        g_part[(b*8 + slot)*TT + threadIdx.x] = t;
    }
}

// F layers: 8 CTAs x 16 columns. Each CTA owns full 64-row columns, so the
// BN over 64 rows is CTA-local.
template<int STAGE>   // 0: parts->y1 (fW0...), 1: y1->y2 (fW1...)
__global__ void k_flayer(const float* __restrict__ W, const float* __restrict__ bias,
                         const float* __restrict__ gamma, const float* __restrict__ beta) {
    __shared__ float s_sm[64*128];
    __shared__ float y_sm[64*16];
    __shared__ float uv[32];
    int tid = threadIdx.x;
    int c0 = blockIdx.x*16;
    for (int idx = tid; idx < 8192; idx += blockDim.x) {
        float v;
        if (STAGE == 0) {
            int r = idx >> 7, k = idx & 127;
            v = 0.f;
            #pragma unroll
            for (int sl = 0; sl < 8; sl++) v += g_part[(r*8 + sl)*128 + k];
        } else v = g_y1[idx];
        s_sm[idx] = v;
    }
    __syncthreads();
    int cl = tid & 15, p = tid >> 4;
    float acc[8];
    #pragma unroll
    for (int rr = 0; rr < 8; rr++) acc[rr] = 0.f;
    for (int k = 0; k < 128; k++) {
        float w = W[k*128 + c0 + cl];
        #pragma unroll
        for (int rr = 0; rr < 8; rr++) acc[rr] += s_sm[(p*8 + rr)*128 + k] * w;
    }
    float bb = bias[c0 + cl];
    #pragma unroll
    for (int rr = 0; rr < 8; rr++) y_sm[(p*8 + rr)*16 + cl] = acc[rr] + bb;
    __syncthreads();
    if (tid < 16) {
        float m = 0.f, q = 0.f;
        for (int r = 0; r < 64; r++) { float y = y_sm[r*16 + tid]; m += y; q += y*y; }
        m *= (1.f/64.f);
        float var = q*(1.f/64.f) - m*m;
        float u = gamma[c0 + tid] * rsqrtf(var + EPS);
        uv[tid] = u; uv[16 + tid] = beta[c0 + tid] - m*u;
    }
    __syncthreads();
    float u = uv[cl], v = uv[16 + cl];
    float* dst = (STAGE == 0) ? g_y1 : g_y2;
    #pragma unroll
    for (int rr = 0; rr < 8; rr++) {
        int r = p*8 + rr;
        dst[r*128 + c0 + cl] = fmaxf(u*y_sm[r*16 + cl] + v, 0.f);
    }
}

__global__ void k_fout(const float* __restrict__ W, const float* __restrict__ bias,
                       float* __restrict__ out) {
    __shared__ float s_sm[8192];
    int tid = threadIdx.x;
    int c0 = blockIdx.x*16;
    for (int idx = tid; idx < 8192; idx += blockDim.x) s_sm[idx] = g_y2[idx];
    __syncthreads();
    int cl = tid & 15, p = tid >> 4;
    float acc[8];
    #pragma unroll
    for (int rr = 0; rr < 8; rr++) acc[rr] = 0.f;
    for (int k = 0; k < 128; k++) {
        float w = W[k*128 + c0 + cl];
        #pragma unroll
        for (int rr = 0; rr < 8; rr++) acc[rr] += s_sm[(p*8 + rr)*128 + k] * w;
    }
    float bb = bias[c0 + cl];
    #pragma unroll
    for (int rr = 0; rr < 8; rr++) out[(p*8 + rr)*128 + c0 + cl] = acc[rr] + bb;
}

// ---------------------------------------------------------------------------
extern "C" void kernel_launch(void* const* d_in, const int* in_sizes, int n_in,
                              void* d_out, int out_size) {
    const float* x   = (const float*)d_in[0];
    const float* gW0 = (const float*)d_in[1];
    const float* gb0 = (const float*)d_in[2];
    const float* gg0 = (const float*)d_in[3];
    const float* gB0 = (const float*)d_in[4];
    const float* gW1 = (const float*)d_in[5];
    const float* gg1 = (const float*)d_in[7];
    const float* gB1 = (const float*)d_in[8];
    const float* gW2 = (const float*)d_in[9];
    const float* gg2 = (const float*)d_in[11];
    const float* gB2 = (const float*)d_in[12];
    const float* fW0 = (const float*)d_in[13];
    const float* fb0 = (const float*)d_in[14];
    const float* fg0 = (const float*)d_in[15];
    const float* fB0 = (const float*)d_in[16];
    const float* fW1 = (const float*)d_in[17];
    const float* fb1 = (const float*)d_in[18];
    const float* fg1 = (const float*)d_in[19];
    const float* fB1 = (const float*)d_in[20];
    const float* foW = (const float*)d_in[21];
    const float* fob = (const float*)d_in[22];
    float* out = (float*)d_out;

    cudaFuncSetAttribute(k_biggemm<1>, cudaFuncAttributeMaxDynamicSharedMemorySize, SM_TOT);
    cudaFuncSetAttribute(k_biggemm<2>, cudaFuncAttributeMaxDynamicSharedMemorySize, SM_TOT);

    void* statsPtr = nullptr;
    cudaGetSymbolAddress(&statsPtr, g_stats);
    cudaMemsetAsync(statsPtr, 0, 1536*sizeof(float), 0);

    k0_splitW<<<384, 256>>>(gW1, gW2);
    k1_computeAB<<<64, 256>>>(x, gW0);
    k2_finalize0<<<1, 256>>>(gb0, gg0, gB0);
    k_biggemm<1><<<dim3(RTOT/MT, 2), 256, SM_TOT>>>();
    k4_finalize1<<<1, 256>>>(gg1, gB1);
    k_biggemm<2><<<dim3(RTOT/MT, 1), 256, SM_TOT>>>();
    k6_finalize2<<<1, 128>>>(gg2, gB2);
    k7_reduce<<<dim3(64, 8), 256>>>();
    k_flayer<0><<<8, 128>>>(fW0, fb0, fg0, fB0);
    k_flayer<1><<<8, 128>>>(fW1, fb1, fg1, fB1);
    k_fout<<<8, 128>>>(foW, fob, out);
}

// round 9
// speedup vs baseline: 1.3486x; 1.3486x over previous
#include <cuda_runtime.h>
#include <cuda_fp16.h>
#include <cstdint>

#define EPS 1e-5f

// ---- problem sizes ----
#define BB 64
#define NN 64
#define DD 64
#define TT 128
#define HG 256
#define RTOT (BB*NN*NN)   // 262144 pair rows

// ---- big-GEMM tiling ----
#define MT 256
#define NT 128
#define KC 128            // K chunk held in smem (2 chunks cover K=256)
#define LDSK 136          // half stride (128 + 8 pad) -> conflict-free LDSM

// ---- device scratch (static: no allocation allowed) ----
__device__ float g_A [BB*NN*HG];     // x @ W0_top   (4096 x 256) fp32 exact
__device__ float g_Bm[BB*NN*HG];     // x @ W0_bot
__device__ float g_SA[BB*HG];
__device__ float g_SB[BB*HG];
// stats: QA[0:256] QB[256:512] S1[512:768] Q1[768:1024] S2[1024:1152] Q2[1152:1280]
__device__ float g_stats[1536];
// coef: u0[0:256] v0[256:512] u1[512:768] v1[768:1024] u2[1024:1152] v2[1152:1280]
__device__ float g_coef[1536];
__device__ float g_z1[(size_t)RTOT*HG];   // 268 MB fp32
__device__ float g_z2[(size_t)RTOT*TT];   // 134 MB fp32
__device__ float g_part[512*TT];
__device__ float g_y1[BB*TT];
__device__ float g_y2[BB*TT];
// W pre-rounded fp16, n-major [n][k]
__device__ __half g_W1t_hi[HG*HG];
__device__ __half g_W2t_hi[TT*HG];

// ---------------------------------------------------------------------------
__device__ __forceinline__ void mma16816(float* c, const uint32_t* a, const uint32_t* b) {
    asm volatile(
        "mma.sync.aligned.m16n8k16.row.col.f32.f16.f16.f32 "
        "{%0,%1,%2,%3}, {%4,%5,%6,%7}, {%8,%9}, {%0,%1,%2,%3};\n"
        : "+f"(c[0]), "+f"(c[1]), "+f"(c[2]), "+f"(c[3])
        : "r"(a[0]), "r"(a[1]), "r"(a[2]), "r"(a[3]), "r"(b[0]), "r"(b[1]));
}

__device__ __forceinline__ void ldsm4(uint32_t* r, uint32_t addr) {
    asm volatile("ldmatrix.sync.aligned.m8n8.x4.shared.b16 {%0,%1,%2,%3}, [%4];"
                 : "=r"(r[0]), "=r"(r[1]), "=r"(r[2]), "=r"(r[3]) : "r"(addr));
}

__device__ __forceinline__ uint32_t smem_u32(const void* p) {
    uint32_t a;
    asm("{ .reg .u64 t; cvta.to.shared.u64 t, %1; cvt.u32.u64 %0, t; }" : "=r"(a) : "l"(p));
    return a;
}

// split fp32 -> (hi, lo) fp16 pair
__device__ __forceinline__ void split_h(float v, __half& hi, __half& lo) {
    hi = __float2half_rn(v);
    lo = __float2half_rn(v - __half2float(hi));
}

// ---------------------------------------------------------------------------
// K0: round W1/W2 to fp16, transposed to n-major [n][k]; also zero the
// accumulation buffers (g_SA/g_SB/g_stats) so no memset launch is needed.
__global__ void k0_splitW(const float* __restrict__ gW1, const float* __restrict__ gW2) {
    int n = blockIdx.x, k = threadIdx.x;  // k 0..255
    if (n < 256) {
        g_W1t_hi[n*HG + k] = __float2half_rn(gW1[k*HG + n]);
    } else {
        int n2 = n - 256;  // 0..127
        g_W2t_hi[n2*HG + k] = __float2half_rn(gW2[k*TT + n2]);
    }
    // zeroing side-duty (runs every replay, before k1's atomics)
    if (n < 64)        g_SA[n*HG + k] = 0.f;
    else if (n < 128)  g_SB[(n - 64)*HG + k] = 0.f;
    else if (n < 134)  g_stats[(n - 128)*256 + k] = 0.f;
}

// K1: A = x @ W0[0:64,:], Bm = x @ W0[64:128,:]; per-batch sums SA/SB (atomic);
// global sums of squares QA/QB. Grid 256 = 64 batches x 4 row-quarters.
__global__ void k1_computeAB(const float* __restrict__ x, const float* __restrict__ gW0) {
    __shared__ float xs[16*DD];
    int b = blockIdx.x >> 2, q = blockIdx.x & 3;
    int c = threadIdx.x;
    for (int idx = threadIdx.x; idx < 16*DD; idx += blockDim.x)
        xs[idx] = x[(b*NN + q*16)*DD + idx];
    __syncthreads();
    float accA[16], accB[16];
    #pragma unroll
    for (int r = 0; r < 16; r++) { accA[r] = 0.f; accB[r] = 0.f; }
    for (int k = 0; k < DD; k++) {
        float wA = gW0[k*HG + c];
        float wB = gW0[(DD + k)*HG + c];
        #pragma unroll
        for (int r = 0; r < 16; r++) {
            float xv = xs[r*DD + k];
            accA[r] += xv * wA;
            accB[r] += xv * wB;
        }
    }
    float sa = 0.f, sb = 0.f, qa = 0.f, qb = 0.f;
    #pragma unroll
    for (int r = 0; r < 16; r++) {
        int row = q*16 + r;
        g_A [(b*NN + row)*HG + c] = accA[r];
        g_Bm[(b*NN + row)*HG + c] = accB[r];
        sa += accA[r]; qa += accA[r]*accA[r];
        sb += accB[r]; qb += accB[r]*accB[r];
    }
    atomicAdd(&g_SA[b*HG + c], sa);
    atomicAdd(&g_SB[b*HG + c], sb);
    atomicAdd(&g_stats[c],      qa);
    atomicAdd(&g_stats[HG + c], qb);
}

// K2: layer-0 BN stats via pair factorization; fold into (u0, v0)
__global__ void k2_finalize0(const float* __restrict__ gb0, const float* __restrict__ gg0,
                             const float* __restrict__ gB0) {
    int c = threadIdx.x;
    float sat = 0.f, sbt = 0.f, p = 0.f;
    for (int b = 0; b < BB; b++) {
        float a = g_SA[b*HG + c], bm = g_SB[b*HG + c];
        sat += a; sbt += bm; p += a*bm;
    }
    float QA = g_stats[c], QB = g_stats[HG + c];
    float g  = gb0[c];
    const float Rf = (float)RTOT;
    float mean = (NN*(sat + sbt))/Rf + g;
    float esq  = (NN*QA + NN*QB + 2.f*p + 2.f*g*NN*(sat + sbt) + Rf*g*g)/Rf;
    float var  = esq - mean*mean;
    float u = gg0[c] * rsqrtf(var + EPS);
    g_coef[c]      = u;
    g_coef[HG + c] = u*(g - mean) + gB0[c];
}

// ---------------------------------------------------------------------------
// Big fused GEMM, 2-term split-fp16 (A exact via hi+lo, W rounded to fp16):
// z = (Ahi + Alo) @ W16. The A-side is exact; the only deviation from the
// reference is a coherent weight perturbation |dW| <= 2^-12|W|, which every
// downstream BN re-normalizes (stats computed on the perturbed values).
extern __shared__ char smem_raw[];

// smem offsets (bytes)
#define SM_HHI 0
#define SM_HLO (MT*LDSK*2)                 // 69632
#define SM_WHI (2*MT*LDSK*2)               // 139264
#define SM_CU  (SM_WHI + NT*LDSK*2)        // 174080
#define SM_CV  (SM_CU + 256*4)
#define SM_SSUM (SM_CV + 256*4)
#define SM_SSQ  (SM_SSUM + 128*4)
#define SM_TOT  (SM_SSQ + 128*4)           // 177152

template<int LAYER>
__global__ __launch_bounds__(512, 1) void k_biggemm() {
    float*  cu  = (float*)(smem_raw + SM_CU);
    float*  cv  = (float*)(smem_raw + SM_CV);
    float*  ssum = (float*)(smem_raw + SM_SSUM);
    float*  ssq  = (float*)(smem_raw + SM_SSQ);

    int tid = threadIdx.x;
    int r0  = blockIdx.x * MT;
    int c0  = blockIdx.y * NT;

    {
        const int coff = (LAYER == 1) ? 0 : 512;
        for (int i = tid; i < 256; i += blockDim.x) {
            cu[i] = g_coef[coff + i];
            cv[i] = g_coef[coff + 256 + i];
        }
        for (int i = tid; i < 128; i += blockDim.x) { ssum[i] = 0.f; ssq[i] = 0.f; }
    }
    __syncthreads();

    int lane = tid & 31, wid = tid >> 5;
    int mw = wid & 7, nw = wid >> 3;           // 8 row-warps x 2 col-warps
    int gq = lane >> 2, tq = lane & 3;

    float acc[2][8][4];
    #pragma unroll
    for (int a = 0; a < 2; a++)
        #pragma unroll
        for (int s = 0; s < 8; s++)
            #pragma unroll
            for (int d = 0; d < 4; d++) acc[a][s][d] = 0.f;

    // LDSM per-lane base addresses (byte offsets into smem)
    const uint32_t sb = smem_u32(smem_raw);
    const uint32_t aRow = (uint32_t)(mw*32 + (lane & 7) + ((lane >> 3) & 1)*8);
    const uint32_t aKof = (uint32_t)(((lane >> 4) & 1)*8);
    const uint32_t aOff = (aRow*LDSK + aKof)*2;
    const uint32_t bRow = (uint32_t)(nw*64 + (lane & 7) + ((lane >> 4) & 1)*8);
    const uint32_t bKof = (uint32_t)(((lane >> 3) & 1)*8);
    const uint32_t bOff = (bRow*LDSK + bKof)*2;
    const uint32_t aHi = sb + SM_HHI + aOff, aLo = sb + SM_HLO + aOff;
    const uint32_t bHi = sb + SM_WHI + bOff;

    const __half* wh = (LAYER == 1) ? (g_W1t_hi + (size_t)c0*HG) : g_W2t_hi;
    const int b = r0 >> 12;
    const int ibase = (r0 >> 6) & 63;

    for (int kc = 0; kc < 2; kc++) {
        if (kc) __syncthreads();   // prior chunk's mma consumers done
        const int kbase = kc * KC;

        // ---- build h tile (MT x KC), hi/lo split ----
        for (int idx = tid; idx < 8192; idx += 512) {
            int r = idx >> 5, c = (idx & 31)*4, cc = kbase + c;
            float v0f, v1f, v2f, v3f;
            if (LAYER == 1) {
                int i = ibase + (r >> 6), j = r & 63;
                float4 av = *(const float4*)&g_A [(size_t)(b*NN + i)*HG + cc];
                float4 bv = *(const float4*)&g_Bm[(size_t)(b*NN + j)*HG + cc];
                v0f = fmaxf(cu[cc  ]*(av.x + bv.x) + cv[cc  ], 0.f);
                v1f = fmaxf(cu[cc+1]*(av.y + bv.y) + cv[cc+1], 0.f);
                v2f = fmaxf(cu[cc+2]*(av.z + bv.z) + cv[cc+2], 0.f);
                v3f = fmaxf(cu[cc+3]*(av.w + bv.w) + cv[cc+3], 0.f);
            } else {
                float4 z = *(const float4*)&g_z1[(size_t)(r0 + r)*HG + cc];
                v0f = fmaxf(cu[cc  ]*z.x + cv[cc  ], 0.f);
                v1f = fmaxf(cu[cc+1]*z.y + cv[cc+1], 0.f);
                v2f = fmaxf(cu[cc+2]*z.z + cv[cc+2], 0.f);
                v3f = fmaxf(cu[cc+3]*z.w + cv[cc+3], 0.f);
            }
            __half h0,l0,h1,l1,h2,l2,h3,l3;
            split_h(v0f,h0,l0); split_h(v1f,h1,l1); split_h(v2f,h2,l2); split_h(v3f,h3,l3);
            uint32_t o = (uint32_t)(r*LDSK + c)*2;
            *(__half2*)(smem_raw + SM_HHI + o)     = __halves2half2(h0, h1);
            *(__half2*)(smem_raw + SM_HHI + o + 4) = __halves2half2(h2, h3);
            *(__half2*)(smem_raw + SM_HLO + o)     = __halves2half2(l0, l1);
            *(__half2*)(smem_raw + SM_HLO + o + 4) = __halves2half2(l2, l3);
        }
        // ---- W chunk (NT n-rows x KC k), pre-rounded fp16, 16B copies ----
        for (int idx = tid; idx < 2048; idx += 512) {
            int n = idx >> 4, ch = (idx & 15)*8;
            uint32_t o = (uint32_t)(n*LDSK + ch)*2;
            *(uint4*)(smem_raw + SM_WHI + o) = *(const uint4*)(wh + (size_t)n*HG + kbase + ch);
        }
        __syncthreads();

        // ---- mma loop: 2 terms, term-outer, 8 LDSM : 32 HMMA per k-slice ----
        for (int ko = 0; ko < KC; ko += 16) {
            uint32_t afh[2][4], afl[2][4];
            ldsm4(afh[0], aHi + (uint32_t)ko*2);
            ldsm4(afh[1], aHi + (uint32_t)(16*LDSK + ko)*2);
            ldsm4(afl[0], aLo + (uint32_t)ko*2);
            ldsm4(afl[1], aLo + (uint32_t)(16*LDSK + ko)*2);
            #pragma unroll
            for (int sp = 0; sp < 4; sp++) {
                uint32_t bh[4];
                ldsm4(bh, bHi + (uint32_t)(sp*16*LDSK + ko)*2);
                // term 0: hi*W  (4 independent accumulators)
                #pragma unroll
                for (int si = 0; si < 2; si++)
                    #pragma unroll
                    for (int mi = 0; mi < 2; mi++)
                        mma16816(acc[mi][sp*2+si], afh[mi], bh + 2*si);
                // term 1: lo*W
                #pragma unroll
                for (int si = 0; si < 2; si++)
                    #pragma unroll
                    for (int mi = 0; mi < 2; mi++)
                        mma16816(acc[mi][sp*2+si], afl[mi], bh + 2*si);
            }
        }
    }

    // ---- epilogue: fp32 store + BN stats ----
    const int ldo = (LAYER == 1) ? HG : TT;
    float* zout = (LAYER == 1) ? g_z1 : g_z2;
    float csum[16], csq[16];
    #pragma unroll
    for (int q = 0; q < 16; q++) { csum[q] = 0.f; csq[q] = 0.f; }
    #pragma unroll
    for (int mi = 0; mi < 2; mi++) {
        int rA = r0 + mw*32 + mi*16 + gq;
        #pragma unroll
        for (int s = 0; s < 8; s++) {
            int cA = c0 + nw*64 + s*8 + 2*tq;
            float d0 = acc[mi][s][0], d1 = acc[mi][s][1], d2 = acc[mi][s][2], d3 = acc[mi][s][3];
            *(float2*)&zout[(size_t)rA*ldo + cA]       = make_float2(d0, d1);
            *(float2*)&zout[(size_t)(rA + 8)*ldo + cA] = make_float2(d2, d3);
            csum[2*s]   += d0 + d2; csq[2*s]   += d0*d0 + d2*d2;
            csum[2*s+1] += d1 + d3; csq[2*s+1] += d1*d1 + d3*d3;
        }
    }
    #pragma unroll
    for (int q = 0; q < 16; q++) {
        #pragma unroll
        for (int off = 4; off < 32; off <<= 1) {
            csum[q] += __shfl_xor_sync(0xffffffffu, csum[q], off);
            csq[q]  += __shfl_xor_sync(0xffffffffu, csq[q],  off);
        }
    }
    if (lane < 4) {
        #pragma unroll
        for (int q = 0; q < 16; q++) {
            int cl = nw*64 + (q >> 1)*8 + 2*tq + (q & 1);
            atomicAdd(&ssum[cl], csum[q]);
            atomicAdd(&ssq[cl],  csq[q]);
        }
    }
    __syncthreads();
    const int soff  = (LAYER == 1) ? 512 : 1024;
    const int sqoff = (LAYER == 1) ? 768 : 1152;
    if (tid < NT) {
        atomicAdd(&g_stats[soff  + c0 + tid], ssum[tid]);
        atomicAdd(&g_stats[sqoff + c0 + tid], ssq[tid]);
    }
}

// K4/K6: fold BN stats into (u, v). Linear bias before BN cancels exactly.
__global__ void k4_finalize1(const float* __restrict__ gg1, const float* __restrict__ gB1) {
    int c = threadIdx.x;  // 256
    float S = g_stats[512 + c], Q = g_stats[768 + c];
    float mean = S / (float)RTOT;
    float var  = Q / (float)RTOT - mean*mean;
    float u = gg1[c] * rsqrtf(var + EPS);
    g_coef[512 + c] = u;
    g_coef[768 + c] = gB1[c] - mean*u;
}
__global__ void k6_finalize2(const float* __restrict__ gg2, const float* __restrict__ gB2) {
    int c = threadIdx.x;  // 128
    float S = g_stats[1024 + c], Q = g_stats[1152 + c];
    float mean = S / (float)RTOT;
    float var  = Q / (float)RTOT - mean*mean;
    float u = gg2[c] * rsqrtf(var + EPS);
    g_coef[1024 + c] = u;
    g_coef[1152 + c] = gB2[c] - mean*u;
}

// K7: pair-sum reduction s[b,c] = sum_p relu(u2*z2 + v2); 8 partial slots per b
__global__ void k7_reduce() {
    __shared__ float red[8][128];
    int b = blockIdx.x, slot = blockIdx.y;
    int cq = threadIdx.x & 31, rg = threadIdx.x >> 5;
    int c = 4*cq;
    float u0 = g_coef[1024 + c],     u1 = g_coef[1024 + c + 1];
    float u2 = g_coef[1024 + c + 2], u3 = g_coef[1024 + c + 3];
    float v0 = g_coef[1152 + c],     v1 = g_coef[1152 + c + 1];
    float v2 = g_coef[1152 + c + 2], v3 = g_coef[1152 + c + 3];
    size_t base = ((size_t)b*4096 + slot*512 + rg*64) * TT;
    float s0 = 0.f, s1 = 0.f, s2 = 0.f, s3 = 0.f;
    for (int rr = 0; rr < 64; rr++) {
        float4 z = *(const float4*)&g_z2[base + (size_t)rr*TT + c];
        s0 += fmaxf(u0*z.x + v0, 0.f);
        s1 += fmaxf(u1*z.y + v1, 0.f);
        s2 += fmaxf(u2*z.z + v2, 0.f);
        s3 += fmaxf(u3*z.w + v3, 0.f);
    }
    red[rg][c] = s0; red[rg][c + 1] = s1; red[rg][c + 2] = s2; red[rg][c + 3] = s3;
    __syncthreads();
    if (threadIdx.x < 128) {
        float t = 0.f;
        #pragma unroll
        for (int g = 0; g < 8; g++) t += red[g][threadIdx.x];
        g_part[(b*8 + slot)*TT + threadIdx.x] = t;
    }
}

// F layers: 8 CTAs x 16 columns. Each CTA owns full 64-row columns, so the
// BN over 64 rows is CTA-local.
template<int STAGE>   // 0: parts->y1 (fW0...), 1: y1->y2 (fW1...)
__global__ void k_flayer(const float* __restrict__ W, const float* __restrict__ bias,
                         const float* __restrict__ gamma, const float* __restrict__ beta) {
    __shared__ float s_sm[64*128];
    __shared__ float y_sm[64*16];
    __shared__ float uv[32];
    int tid = threadIdx.x;
    int c0 = blockIdx.x*16;
    for (int idx = tid; idx < 8192; idx += blockDim.x) {
        float v;
        if (STAGE == 0) {
            int r = idx >> 7, k = idx & 127;
            v = 0.f;
            #pragma unroll
            for (int sl = 0; sl < 8; sl++) v += g_part[(r*8 + sl)*128 + k];
        } else v = g_y1[idx];
        s_sm[idx] = v;
    }
    __syncthreads();
    int cl = tid & 15, p = tid >> 4;
    float acc[8];
    #pragma unroll
    for (int rr = 0; rr < 8; rr++) acc[rr] = 0.f;
    for (int k = 0; k < 128; k++) {
        float w = W[k*128 + c0 + cl];
        #pragma unroll
        for (int rr = 0; rr < 8; rr++) acc[rr] += s_sm[(p*8 + rr)*128 + k] * w;
    }
    float bb = bias[c0 + cl];
    #pragma unroll
    for (int rr = 0; rr < 8; rr++) y_sm[(p*8 + rr)*16 + cl] = acc[rr] + bb;
    __syncthreads();
    if (tid < 16) {
        float m = 0.f, q = 0.f;
        for (int r = 0; r < 64; r++) { float y = y_sm[r*16 + tid]; m += y; q += y*y; }
        m *= (1.f/64.f);
        float var = q*(1.f/64.f) - m*m;
        float u = gamma[c0 + tid] * rsqrtf(var + EPS);
        uv[tid] = u; uv[16 + tid] = beta[c0 + tid] - m*u;
    }
    __syncthreads();
    float u = uv[cl], v = uv[16 + cl];
    float* dst = (STAGE == 0) ? g_y1 : g_y2;
    #pragma unroll
    for (int rr = 0; rr < 8; rr++) {
        int r = p*8 + rr;
        dst[r*128 + c0 + cl] = fmaxf(u*y_sm[r*16 + cl] + v, 0.f);
    }
}

__global__ void k_fout(const float* __restrict__ W, const float* __restrict__ bias,
                       float* __restrict__ out) {
    __shared__ float s_sm[8192];
    int tid = threadIdx.x;
    int c0 = blockIdx.x*16;
    for (int idx = tid; idx < 8192; idx += blockDim.x) s_sm[idx] = g_y2[idx];
    __syncthreads();
    int cl = tid & 15, p = tid >> 4;
    float acc[8];
    #pragma unroll
    for (int rr = 0; rr < 8; rr++) acc[rr] = 0.f;
    for (int k = 0; k < 128; k++) {
        float w = W[k*128 + c0 + cl];
        #pragma unroll
        for (int rr = 0; rr < 8; rr++) acc[rr] += s_sm[(p*8 + rr)*128 + k] * w;
    }
    float bb = bias[c0 + cl];
    #pragma unroll
    for (int rr = 0; rr < 8; rr++) out[(p*8 + rr)*128 + c0 + cl] = acc[rr] + bb;
}

// ---------------------------------------------------------------------------
extern "C" void kernel_launch(void* const* d_in, const int* in_sizes, int n_in,
                              void* d_out, int out_size) {
    const float* x   = (const float*)d_in[0];
    const float* gW0 = (const float*)d_in[1];
    const float* gb0 = (const float*)d_in[2];
    const float* gg0 = (const float*)d_in[3];
    const float* gB0 = (const float*)d_in[4];
    const float* gW1 = (const float*)d_in[5];
    const float* gg1 = (const float*)d_in[7];
    const float* gB1 = (const float*)d_in[8];
    const float* gW2 = (const float*)d_in[9];
    const float* gg2 = (const float*)d_in[11];
    const float* gB2 = (const float*)d_in[12];
    const float* fW0 = (const float*)d_in[13];
    const float* fb0 = (const float*)d_in[14];
    const float* fg0 = (const float*)d_in[15];
    const float* fB0 = (const float*)d_in[16];
    const float* fW1 = (const float*)d_in[17];
    const float* fb1 = (const float*)d_in[18];
    const float* fg1 = (const float*)d_in[19];
    const float* fB1 = (const float*)d_in[20];
    const float* foW = (const float*)d_in[21];
    const float* fob = (const float*)d_in[22];
    float* out = (float*)d_out;

    cudaFuncSetAttribute(k_biggemm<1>, cudaFuncAttributeMaxDynamicSharedMemorySize, SM_TOT);
    cudaFuncSetAttribute(k_biggemm<2>, cudaFuncAttributeMaxDynamicSharedMemorySize, SM_TOT);

    k0_splitW<<<384, 256>>>(gW1, gW2);
    k1_computeAB<<<256, 256>>>(x, gW0);
    k2_finalize0<<<1, 256>>>(gb0, gg0, gB0);
    k_biggemm<1><<<dim3(RTOT/MT, 2), 512, SM_TOT>>>();
    k4_finalize1<<<1, 256>>>(gg1, gB1);
    k_biggemm<2><<<dim3(RTOT/MT, 1), 512, SM_TOT>>>();
    k6_finalize2<<<1, 128>>>(gg2, gB2);
    k7_reduce<<<dim3(64, 8), 256>>>();
    k_flayer<0><<<8, 128>>>(fW0, fb0, fg0, fB0);
    k_flayer<1><<<8, 128>>>(fW1, fb1, fg1, fB1);
    k_fout<<<8, 128>>>(foW, fob, out);
}